// round 3
// baseline (speedup 1.0000x reference)
#include <cuda_runtime.h>

#define NN   100000
#define INF  128
#define OUTF 64

// Scratch (allocation-free rule: __device__ globals; guaranteed global space)
__device__ float g_xws[(size_t)NN * OUTF];   // (X@W) * rsqrt(deg_out), per node
__device__ float g_agg[(size_t)NN * OUTF];   // atomic accumulator
__device__ int   g_deg_out[NN];
__device__ int   g_deg_in[NN];

// ---------------------------------------------------------------------------
// Zero the scratch accumulator and the degree counters
// ---------------------------------------------------------------------------
__global__ void zero_kernel() {
    int stride = gridDim.x * blockDim.x;
    int t = blockIdx.x * blockDim.x + threadIdx.x;
    int n4 = NN * OUTF / 4;
    float4* agg4 = (float4*)g_agg;
    for (int j = t; j < n4; j += stride)
        agg4[j] = make_float4(0.f, 0.f, 0.f, 0.f);
    for (int j = t; j < NN; j += stride) {
        g_deg_out[j] = 0;
        g_deg_in[j]  = 0;
    }
}

// ---------------------------------------------------------------------------
// Degree histogram: 2 int atomics per edge, spread addresses (L2 atomics)
// src/dst are int32 (JAX default x64-disabled downgrades int64 -> int32).
// ---------------------------------------------------------------------------
__global__ void degree_kernel(const int* __restrict__ src,
                              const int* __restrict__ dst, int E) {
    int stride = gridDim.x * blockDim.x;
    for (int e = blockIdx.x * blockDim.x + threadIdx.x; e < E; e += stride) {
        int s = src[e], d = dst[e];
        if ((unsigned)s < NN) atomicAdd(&g_deg_out[s], 1);
        if ((unsigned)d < NN) atomicAdd(&g_deg_in[d],  1);
    }
}

// ---------------------------------------------------------------------------
// xws = (X @ W) * rsqrt(max(deg_out,1))
// Block: 64 rows x 64 cols, 256 threads, thread tile 4x4 (register tiled).
// ---------------------------------------------------------------------------
__global__ __launch_bounds__(256) void gemm_scale_kernel(
    const float* __restrict__ A, const float* __restrict__ W, int n) {
    __shared__ float Ws[INF][OUTF];
    int tid = threadIdx.x;
    for (int i = tid; i < INF * OUTF / 4; i += 256)
        ((float4*)Ws)[i] = ((const float4*)W)[i];
    __syncthreads();

    int ty = tid >> 4;           // 0..15 -> row group
    int tx = tid & 15;           // 0..15 -> col group (4 cols each)
    int row0 = blockIdx.x * 64 + ty * 4;

    float acc[4][4] = {};
    const float4* Ar[4];
    #pragma unroll
    for (int m = 0; m < 4; m++) {
        int r = row0 + m;
        if (r >= n) r = n - 1;   // clamp; result discarded on store
        Ar[m] = (const float4*)(A + (size_t)r * INF);
    }

    for (int k4 = 0; k4 < INF / 4; k4++) {
        float4 a[4];
        #pragma unroll
        for (int m = 0; m < 4; m++) a[m] = __ldg(&Ar[m][k4]);
        #pragma unroll
        for (int kk = 0; kk < 4; kk++) {
            float4 w = *(const float4*)&Ws[k4 * 4 + kk][tx * 4];
            #pragma unroll
            for (int m = 0; m < 4; m++) {
                float av = (kk == 0) ? a[m].x : (kk == 1) ? a[m].y
                         : (kk == 2) ? a[m].z : a[m].w;
                acc[m][0] = fmaf(av, w.x, acc[m][0]);
                acc[m][1] = fmaf(av, w.y, acc[m][1]);
                acc[m][2] = fmaf(av, w.z, acc[m][2]);
                acc[m][3] = fmaf(av, w.w, acc[m][3]);
            }
        }
    }

    #pragma unroll
    for (int m = 0; m < 4; m++) {
        int r = row0 + m;
        if (r < n) {
            int dg = g_deg_out[r];
            float s = rsqrtf((float)(dg > 0 ? dg : 1));
            float4 v = make_float4(acc[m][0] * s, acc[m][1] * s,
                                   acc[m][2] * s, acc[m][3] * s);
            *(float4*)&g_xws[(size_t)r * OUTF + tx * 4] = v;
        }
    }
}

// ---------------------------------------------------------------------------
// Edge scatter: g_agg[dst] += g_xws[src]. 16 lanes per edge, each lane owns
// one float4 (16B). red.global.add.v4.f32 = fire-and-forget vector reduction
// into our own device-global scratch.
// ---------------------------------------------------------------------------
__global__ __launch_bounds__(256) void scatter_kernel(
    const int* __restrict__ src, const int* __restrict__ dst, int E) {
    int gid     = (blockIdx.x * blockDim.x + threadIdx.x) >> 4;
    int lane    = threadIdx.x & 15;
    int ngroups = (gridDim.x * blockDim.x) >> 4;
    for (int e = gid; e < E; e += ngroups) {
        int s = __ldg(&src[e]);
        int d = __ldg(&dst[e]);
        if ((unsigned)s >= NN || (unsigned)d >= NN) continue;
        float4 v = __ldg((const float4*)(g_xws + (size_t)s * OUTF) + lane);
        float* p = g_agg + (size_t)d * OUTF + lane * 4;
        asm volatile("red.global.add.v4.f32 [%0], {%1, %2, %3, %4};"
                     :: "l"(p), "f"(v.x), "f"(v.y), "f"(v.z), "f"(v.w)
                     : "memory");
    }
}

// ---------------------------------------------------------------------------
// out = relu(g_agg * rsqrt(max(deg_in,1)) + b)   (plain stores to d_out)
// ---------------------------------------------------------------------------
__global__ void finalize_kernel(float* __restrict__ out,
                                const float* __restrict__ b, int n) {
    int total4 = n * (OUTF / 4);
    int stride = gridDim.x * blockDim.x;
    const float4* agg4 = (const float4*)g_agg;
    for (int j = blockIdx.x * blockDim.x + threadIdx.x; j < total4; j += stride) {
        int node = j >> 4;            // 16 float4 per node
        int c4   = (j & 15) * 4;
        int dg = g_deg_in[node];
        float s = rsqrtf((float)(dg > 0 ? dg : 1));
        float4 v = agg4[j];
        v.x = fmaxf(fmaf(v.x, s, b[c4 + 0]), 0.f);
        v.y = fmaxf(fmaf(v.y, s, b[c4 + 1]), 0.f);
        v.z = fmaxf(fmaf(v.z, s, b[c4 + 2]), 0.f);
        v.w = fmaxf(fmaf(v.w, s, b[c4 + 3]), 0.f);
        ((float4*)out)[j] = v;
    }
}

// ---------------------------------------------------------------------------
// Inputs (metadata order): in_feat f32 [N*128], src i32 [E], dst i32 [E],
//                          W f32 [128*64], b f32 [64]. Output f32 [N*64].
// ---------------------------------------------------------------------------
extern "C" void kernel_launch(void* const* d_in, const int* in_sizes, int n_in,
                              void* d_out, int out_size) {
    const float* in_feat = (const float*)d_in[0];
    const int*   src     = (const int*)d_in[1];
    const int*   dst     = (const int*)d_in[2];
    const float* W       = (const float*)d_in[3];
    const float* b       = (const float*)d_in[4];
    float*       out     = (float*)d_out;

    int n = in_sizes[0] / INF;
    int E = in_sizes[1];

    zero_kernel<<<2048, 256>>>();
    degree_kernel<<<2048, 256>>>(src, dst, E);
    gemm_scale_kernel<<<(n + 63) / 64, 256>>>(in_feat, W, n);
    scatter_kernel<<<8192, 256>>>(src, dst, E);
    finalize_kernel<<<2048, 256>>>(out, b, n);
}